// round 17
// baseline (speedup 1.0000x reference)
#include <cuda_runtime.h>
#include <cuda_bf16.h>
#include <cuda_fp16.h>
#include <cstdint>

#define B 512
#define EDIM 200
#define NUM_ENT 100000
#define FDIM 4608          // 32*8*18
#define KFC 4608
#define EPS 1e-5f
#define KH 256             // fp16 K padded 200 -> 256
#define ENT_TILE 256
#define N_GRID ((NUM_ENT + ENT_TILE - 1) / ENT_TILE)   // 391
#define ENT_PAD (N_GRID * ENT_TILE)                    // 100096
#define ESEGS (NUM_ENT * 25)                           // 2.5M 8-col segments
#define PREPE_GRID ((ESEGS + 255) / 256)               // 9766
#define WSEGS (EDIM * (KFC / 8))                       // 115200
#define PREPW_GRID ((WSEGS + 255) / 256)               // 451

// ---------------- device scratch (static allocations only; zero-initialized) ----------------
__device__ __half d_yh[B * KFC];           // conv output, RAW fp16 (pre-bn1)
__device__ float d_h[B * EDIM];            // fc output, pre-bn2 (zeroed per call by prep_w)
__device__ __half d_wcat[256 * KFC];       // fc_w fp16; rows 200..255 never written (stay 0)
__device__ __half d_zcat[B * KH];          // fp16 z; cols 200..255 never written (stay 0)
__device__ __half d_ecat[ENT_PAD * KH];    // fp16 e; pad rows/cols never written (stay 0)
__device__ float d_chsumB[16][32];         // bn1 partials; bucket b zeroed by k1 block b
__device__ float d_chsqB[16][32];
__device__ float d_bn0B[16][2];            // bn0 partials; STORED (not accumulated) by k1

// ---------------- PTX helpers (sm_80-compatible subset only) ----------------
__device__ __forceinline__ uint32_t smem_u32(const void* p) {
    uint32_t a;
    asm("{ .reg .u64 t; cvta.to.shared.u64 t, %1; cvt.u32.u64 %0, t; }" : "=r"(a) : "l"(p));
    return a;
}
__device__ __forceinline__ void cp_async16(uint32_t dst, const void* src) {
    asm volatile("cp.async.cg.shared.global [%0], [%1], 16;" :: "r"(dst), "l"(src) : "memory");
}
__device__ __forceinline__ void cp_commit() {
    asm volatile("cp.async.commit_group;" ::: "memory");
}
__device__ __forceinline__ void ldm4(uint32_t* r, uint32_t a) {
    asm volatile("ldmatrix.sync.aligned.m8n8.x4.shared.b16 {%0,%1,%2,%3}, [%4];"
                 : "=r"(r[0]), "=r"(r[1]), "=r"(r[2]), "=r"(r[3]) : "r"(a));
}
__device__ __forceinline__ void mma16816h(float* d, const uint32_t* a, const uint32_t* b) {
    asm volatile("mma.sync.aligned.m16n8k16.row.col.f32.f16.f16.f32 "
                 "{%0,%1,%2,%3}, {%4,%5,%6,%7}, {%8,%9}, {%0,%1,%2,%3};"
                 : "+f"(d[0]), "+f"(d[1]), "+f"(d[2]), "+f"(d[3])
                 : "r"(a[0]), "r"(a[1]), "r"(a[2]), "r"(a[3]), "r"(b[0]), "r"(b[1]));
}
__device__ __forceinline__ uint32_t swz(uint32_t off) { return off ^ ((off >> 3) & 0x70); }
__device__ __forceinline__ uint32_t pack_h2(__half a, __half b) {
    return (uint32_t)__half_as_ushort(a) | ((uint32_t)__half_as_ushort(b) << 16);
}
__device__ __forceinline__ float sigmoid_fast(float v) {
    float t;
    asm("tanh.approx.f32 %0, %1;" : "=f"(t) : "f"(0.5f * v));
    return fmaf(0.5f, t, 0.5f);
}

// ---------------- prep_w (side stream): fc_w->fp16 + zero d_h ----------------
__global__ void __launch_bounds__(256) k_prep_w(const float* __restrict__ fc_w) {
    int gi = blockIdx.x * 256 + threadIdx.x;
    if (gi < B * EDIM) d_h[gi] = 0.f;
    if (gi < WSEGS) {
        int row = gi / (KFC / 8), c0 = (gi % (KFC / 8)) * 8;
        const float* src = fc_w + (size_t)row * KFC + c0;
        float4 f0 = *(const float4*)src;
        float4 f1 = *(const float4*)(src + 4);
        uint32_t p0 = pack_h2(__float2half(f0.x), __float2half(f0.y));
        uint32_t p1 = pack_h2(__float2half(f0.z), __float2half(f0.w));
        uint32_t p2 = pack_h2(__float2half(f1.x), __float2half(f1.y));
        uint32_t p3 = pack_h2(__float2half(f1.z), __float2half(f1.w));
        *(uint4*)(d_wcat + (size_t)row * KFC + c0) = make_uint4(p0, p1, p2, p3);
    }
}

// ---------------- prep_e (side stream): emb -> fp16 ecat ----------------
__global__ void __launch_bounds__(256) k_prep_e(const float* __restrict__ emb) {
    int gi = blockIdx.x * 256 + threadIdx.x;
    if (gi < ESEGS) {
        int row = gi / 25, c0 = (gi - row * 25) * 8;
        const float* src = emb + (size_t)row * EDIM + c0;
        float4 f0 = *(const float4*)src;
        float4 f1 = *(const float4*)(src + 4);
        uint32_t p0 = pack_h2(__float2half(f0.x), __float2half(f0.y));
        uint32_t p1 = pack_h2(__float2half(f0.z), __float2half(f0.w));
        uint32_t p2 = pack_h2(__float2half(f1.x), __float2half(f1.y));
        uint32_t p3 = pack_h2(__float2half(f1.z), __float2half(f1.w));
        *(uint4*)(d_ecat + (size_t)row * KH + c0) = make_uint4(p0, p1, p2, p3);
    }
}

// ---------------- K1 (main): bn0 stats; block-reduce + STORE; zero own bn1 bucket ----------------
__global__ void k1_bn0(const int* __restrict__ e1, const float* __restrict__ emb) {
    __shared__ float ws[16], wq[16];
    int tid = threadIdx.x, lane = tid & 31, wrp = tid >> 5;
    if (tid < 32) { d_chsumB[blockIdx.x][tid] = 0.f; d_chsqB[blockIdx.x][tid] = 0.f; }
    float s = 0.f, q = 0.f;
    for (int idx = blockIdx.x * 512 + tid; idx < B * EDIM; idx += gridDim.x * 512) {
        int b = idx / EDIM, j = idx - b * EDIM;
        float v = emb[(size_t)e1[b] * EDIM + j];
        s += v; q += v * v;
    }
    #pragma unroll
    for (int o = 16; o; o >>= 1) {
        s += __shfl_down_sync(0xffffffffu, s, o);
        q += __shfl_down_sync(0xffffffffu, q, o);
    }
    if (lane == 0) { ws[wrp] = s; wq[wrp] = q; }
    __syncthreads();
    if (tid < 16) {
        float v1 = ws[tid], v2 = wq[tid];
        #pragma unroll
        for (int o = 8; o; o >>= 1) {
            v1 += __shfl_down_sync(0xffffu, v1, o, 16);
            v2 += __shfl_down_sync(0xffffu, v2, o, 16);
        }
        if (tid == 0) { d_bn0B[blockIdx.x][0] = v1; d_bn0B[blockIdx.x][1] = v2; }
    }
}

// ---------------- K2 (main): conv; smem-staged; fp16 flush ----------------
__global__ void k2_conv(const int* __restrict__ e1, const int* __restrict__ rel,
                        const float* __restrict__ emb,
                        const float* __restrict__ conv_w, const float* __restrict__ conv_b,
                        const float* __restrict__ g0, const float* __restrict__ b0) {
    __shared__ float sx[200];
    __shared__ float sw[288];
    __shared__ float scb[32];
    __shared__ float sbn[2];
    __shared__ __align__(16) float sy[FDIM];   // 18 KB staging
    int b = blockIdx.x;
    int tid = threadIdx.x;
    int r = rel[b];

    if (tid < 32) {
        float v = (tid < 16) ? d_bn0B[tid][0] : d_bn0B[tid - 16][1];
        #pragma unroll
        for (int o = 8; o; o >>= 1) v += __shfl_down_sync(0xffffffffu, v, o, 16);
        if ((tid & 15) == 0) sbn[tid >> 4] = v;
    }
    __syncthreads();
    const float inv0 = 1.f / (float)(B * EDIM);
    float m0v = sbn[0] * inv0;
    float var0 = sbn[1] * inv0 - m0v * m0v;
    float bn_s = rsqrtf(var0 + EPS) * g0[0];
    float bn_b = b0[0] - m0v * bn_s;

    if (tid < 200) sx[tid] = fmaf(emb[(size_t)e1[b] * EDIM + tid], bn_s, bn_b);
    for (int i = tid; i < 288; i += 256) sw[i] = conv_w[(size_t)r * 288 + i];
    if (tid < 32) scb[tid] = conv_b[(size_t)r * 32 + tid];
    __syncthreads();

    int o = tid >> 3;
    int i = tid & 7;
    const float* w = &sw[o * 9];
    float cb = scb[o];
    float ls = 0.f, lq = 0.f;
    float* syrow = &sy[o * 144 + i * 18];
    #pragma unroll
    for (int j = 0; j < 18; j++) {
        float acc = cb;
        #pragma unroll
        for (int di = 0; di < 3; di++)
            #pragma unroll
            for (int dj = 0; dj < 3; dj++)
                acc = fmaf(sx[(i + di) * 20 + (j + dj)], w[di * 3 + dj], acc);
        syrow[j] = acc;
        ls += acc; lq += acc * acc;
    }
    #pragma unroll
    for (int off = 4; off; off >>= 1) {
        ls += __shfl_down_sync(0xffffffffu, ls, off, 8);
        lq += __shfl_down_sync(0xffffffffu, lq, off, 8);
    }
    if ((tid & 7) == 0) {
        atomicAdd(&d_chsumB[b & 15][o], ls);
        atomicAdd(&d_chsqB[b & 15][o], lq);
    }
    __syncthreads();

    // fp16 flush: 576 segments of 8, coalesced uint4 stores
    __half* dst = d_yh + (size_t)b * KFC;
    #pragma unroll
    for (int s = 0; s < 2; s++) {
        int seg = tid + s * 256;
        const float* sp = sy + seg * 8;
        uint32_t p0 = pack_h2(__float2half(sp[0]), __float2half(sp[1]));
        uint32_t p1 = pack_h2(__float2half(sp[2]), __float2half(sp[3]));
        uint32_t p2 = pack_h2(__float2half(sp[4]), __float2half(sp[5]));
        uint32_t p3 = pack_h2(__float2half(sp[6]), __float2half(sp[7]));
        *(uint4*)(dst + seg * 8) = make_uint4(p0, p1, p2, p3);
    }
    {
        int seg = tid + 512;
        if (seg < KFC / 8) {
            const float* sp = sy + seg * 8;
            uint32_t p0 = pack_h2(__float2half(sp[0]), __float2half(sp[1]));
            uint32_t p1 = pack_h2(__float2half(sp[2]), __float2half(sp[3]));
            uint32_t p2 = pack_h2(__float2half(sp[4]), __float2half(sp[5]));
            uint32_t p3 = pack_h2(__float2half(sp[6]), __float2half(sp[7]));
            *(uint4*)(dst + seg * 8) = make_uint4(p0, p1, p2, p3);
        }
    }
}

// ---------------- K3 (main, after prep_w join): fc GEMM, 72 single-chunk k-splits ----------------
#define F_TA 0
#define F_TB 8192
#define F_SMEM 24576

__global__ void __launch_bounds__(256) k3_mma(const float* __restrict__ g1,
                                              const float* __restrict__ b1) {
    extern __shared__ char smem[];
    const uint32_t sb = smem_u32(smem);
    __shared__ float s_a[32], s_c[32];
    int tid = threadIdx.x, lane = tid & 31, wid = tid >> 5;
    int wm = wid & 1, wn = wid >> 1;
    int n0 = blockIdx.x * 128, m0 = blockIdx.y * 64;
    int kcol = blockIdx.z * 64;

    if (tid < 32) {
        float cs = 0.f, cq = 0.f;
        #pragma unroll
        for (int j = 0; j < 16; j++) { cs += d_chsumB[j][tid]; cq += d_chsqB[j][tid]; }
        const float inv = 1.f / (float)(B * 144);
        float m = cs * inv;
        float var = cq * inv - m * m;
        float a = rsqrtf(var + EPS) * g1[tid];
        s_a[tid] = a;
        s_c[tid] = b1[tid] - m * a;
    }

    // B chunk: 128 rows x 64 cols via cp.async (overlaps with A transform below)
    #pragma unroll
    for (int i = 0; i < 4; i++) {
        int idx = tid + i * 256;
        int row = idx >> 3, u = idx & 7;
        cp_async16(sb + F_TB + swz(row * 128 + u * 16),
                   d_wcat + (size_t)(n0 + row) * KFC + kcol + u * 8);
    }
    cp_commit();
    __syncthreads();      // s_a/s_c visible

    // A chunk: 64 rows x 64 cols, fp16 load -> bn1 affine + relu -> fp16 STS
    #pragma unroll
    for (int i = 0; i < 2; i++) {
        int idx = tid + i * 256;
        int row = idx >> 3, u = idx & 7;
        uint4 raw = *(const uint4*)(d_yh + (size_t)(m0 + row) * KFC + kcol + u * 8);
        const uint32_t rr[4] = {raw.x, raw.y, raw.z, raw.w};
        uint32_t p[4];
        #pragma unroll
        for (int t2 = 0; t2 < 4; t2++) {
            int ka = kcol + u * 8 + 2 * t2;
            int ca = ka / 144, cb = (ka + 1) / 144;
            float va = __half2float(__ushort_as_half((unsigned short)(rr[t2] & 0xffffu)));
            float vb = __half2float(__ushort_as_half((unsigned short)(rr[t2] >> 16)));
            __half ha = __float2half(fmaxf(fmaf(va, s_a[ca], s_c[ca]), 0.f));
            __half hb = __float2half(fmaxf(fmaf(vb, s_a[cb], s_c[cb]), 0.f));
            p[t2] = pack_h2(ha, hb);
        }
        *(uint4*)(smem + F_TA + swz(row * 128 + u * 16)) = make_uint4(p[0], p[1], p[2], p[3]);
    }

    float acc[2][4][4];
    #pragma unroll
    for (int f = 0; f < 2; f++)
        #pragma unroll
        for (int h = 0; h < 4; h++)
            #pragma unroll
            for (int i = 0; i < 4; i++) acc[f][h][i] = 0.f;

    asm volatile("cp.async.wait_group 0;" ::: "memory");
    __syncthreads();

    #pragma unroll
    for (int s = 0; s < 4; s++) {
        uint32_t a[2][4];
        #pragma unroll
        for (int f = 0; f < 2; f++) {
            int row = wm * 32 + f * 16 + (lane & 15);
            int u = s * 2 + (lane >> 4);
            ldm4(a[f], sb + F_TA + swz(row * 128 + u * 16));
        }
        #pragma unroll
        for (int j = 0; j < 2; j++) {
            uint32_t b[4];
            int row = wn * 32 + j * 16 + ((lane >> 4) << 3) + (lane & 7);
            int u = s * 2 + ((lane >> 3) & 1);
            ldm4(b, sb + F_TB + swz(row * 128 + u * 16));
            #pragma unroll
            for (int g = 0; g < 2; g++)
                #pragma unroll
                for (int f = 0; f < 2; f++)
                    mma16816h(acc[f][j * 2 + g], a[f], b + g * 2);
        }
    }

    int g = lane >> 2, q = lane & 3;
    #pragma unroll
    for (int f = 0; f < 2; f++) {
        int mrow = m0 + wm * 32 + f * 16 + g;
        #pragma unroll
        for (int h = 0; h < 4; h++) {
            int n = n0 + wn * 32 + h * 8 + q * 2;
            if (n < EDIM) {
                atomicAdd(&d_h[(size_t)mrow * EDIM + n],           acc[f][h][0]);
                atomicAdd(&d_h[(size_t)mrow * EDIM + n + 1],       acc[f][h][1]);
                atomicAdd(&d_h[(size_t)(mrow + 8) * EDIM + n],     acc[f][h][2]);
                atomicAdd(&d_h[(size_t)(mrow + 8) * EDIM + n + 1], acc[f][h][3]);
            }
        }
    }
}

// ---------------- K4 (main): bn2 + relu, emit fp16 z ----------------
__global__ void k4_bn2(const float* __restrict__ g2, const float* __restrict__ b2) {
    int n = blockIdx.x;
    int t = threadIdx.x;
    float v0 = d_h[(size_t)t * EDIM + n];
    float v1 = d_h[(size_t)(t + 256) * EDIM + n];
    __shared__ float rs[256], rq[256];
    rs[t] = v0 + v1; rq[t] = v0 * v0 + v1 * v1;
    __syncthreads();
    for (int o = 128; o; o >>= 1) {
        if (t < o) { rs[t] += rs[t + o]; rq[t] += rq[t + o]; }
        __syncthreads();
    }
    __shared__ float sa, sc;
    if (t == 0) {
        float m = rs[0] * (1.f / 512.f);
        float var = rq[0] * (1.f / 512.f) - m * m;
        float a = rsqrtf(var + EPS) * g2[n];
        sa = a; sc = b2[n] - m * a;
    }
    __syncthreads();
    float z0 = fmaxf(fmaf(v0, sa, sc), 0.f);
    float z1 = fmaxf(fmaf(v1, sa, sc), 0.f);
    d_zcat[(size_t)t * KH + n]         = __float2half(z0);
    d_zcat[(size_t)(t + 256) * KH + n] = __float2half(z1);
}

// ---------------- K5 (main, after prep_e join): fp16 mma GEMM + bias + sigmoid ----------------
#define T_A 0
#define T_B 8192
#define ST_STRIDE 40960
#define K5_SMEM (2 * ST_STRIDE)

__device__ __forceinline__ void k5_load(uint32_t sb, int buf, int ks, int m0, int n0, int tid) {
    uint32_t base = sb + buf * ST_STRIDE;
    int koff = ks * 64;
    if (ks < 3) {
        #pragma unroll
        for (int i = 0; i < 2; i++) {
            int idx = tid + i * 256;
            int row = idx >> 3, u = idx & 7;
            cp_async16(base + T_A + swz(row * 128 + u * 16),
                       d_zcat + (size_t)(m0 + row) * KH + koff + u * 8);
        }
        #pragma unroll
        for (int i = 0; i < 8; i++) {
            int idx = tid + i * 256;
            int row = idx >> 3, u = idx & 7;
            cp_async16(base + T_B + swz(row * 128 + u * 16),
                       d_ecat + (size_t)(n0 + row) * KH + koff + u * 8);
        }
    } else {
        if (tid < 128) {
            int row = tid >> 1, u = tid & 1;
            cp_async16(base + T_A + swz(row * 128 + u * 16),
                       d_zcat + (size_t)(m0 + row) * KH + koff + u * 8);
        }
        #pragma unroll
        for (int i = 0; i < 2; i++) {
            int idx = tid + i * 256;
            int row = idx >> 1, u = idx & 1;
            cp_async16(base + T_B + swz(row * 128 + u * 16),
                       d_ecat + (size_t)(n0 + row) * KH + koff + u * 8);
        }
    }
    cp_commit();
}

__global__ void __launch_bounds__(256, 2) k5_mma(const float* __restrict__ bias_e,
                                                 float* __restrict__ out) {
    extern __shared__ char smem[];
    const uint32_t sb = smem_u32(smem);
    int tid = threadIdx.x, lane = tid & 31, wid = tid >> 5;
    int wm = wid & 1, wn = wid >> 1;
    int m0 = blockIdx.x * 64, n0 = blockIdx.y * 256;

    float acc[2][8][4];
    #pragma unroll
    for (int f = 0; f < 2; f++)
        #pragma unroll
        for (int h = 0; h < 8; h++)
            #pragma unroll
            for (int i = 0; i < 4; i++) acc[f][h][i] = 0.f;

    k5_load(sb, 0, 0, m0, n0, tid);

    for (int ks = 0; ks < 4; ks++) {
        int buf = ks & 1;
        if (ks < 3) {
            k5_load(sb, buf ^ 1, ks + 1, m0, n0, tid);
            asm volatile("cp.async.wait_group 1;" ::: "memory");
        } else {
            asm volatile("cp.async.wait_group 0;" ::: "memory");
        }
        __syncthreads();

        const int scount = (ks < 3) ? 4 : 1;
        const uint32_t st = sb + buf * ST_STRIDE;
        for (int s = 0; s < scount; s++) {
            uint32_t a[2][4];
            #pragma unroll
            for (int f = 0; f < 2; f++) {
                int row = wm * 32 + f * 16 + (lane & 15);
                int u = s * 2 + (lane >> 4);
                ldm4(a[f], st + T_A + swz(row * 128 + u * 16));
            }
            #pragma unroll
            for (int j = 0; j < 4; j++) {
                uint32_t b[4];
                int row = wn * 64 + j * 16 + ((lane >> 4) << 3) + (lane & 7);
                int u = s * 2 + ((lane >> 3) & 1);
                ldm4(b, st + T_B + swz(row * 128 + u * 16));
                #pragma unroll
                for (int g = 0; g < 2; g++)
                    #pragma unroll
                    for (int f = 0; f < 2; f++)
                        mma16816h(acc[f][j * 2 + g], a[f], b + g * 2);
            }
        }
        __syncthreads();
    }

    int g = lane >> 2, q = lane & 3;
    #pragma unroll
    for (int f = 0; f < 2; f++) {
        int mrow = m0 + wm * 32 + f * 16 + g;
        #pragma unroll
        for (int h = 0; h < 8; h++) {
            int n = n0 + wn * 64 + h * 8 + q * 2;
            if (n < NUM_ENT) {
                float b0 = bias_e[n], b1 = bias_e[n + 1];
                *(float2*)&out[(size_t)mrow * NUM_ENT + n] =
                    make_float2(sigmoid_fast(acc[f][h][0] + b0),
                                sigmoid_fast(acc[f][h][1] + b1));
                *(float2*)&out[(size_t)(mrow + 8) * NUM_ENT + n] =
                    make_float2(sigmoid_fast(acc[f][h][2] + b0),
                                sigmoid_fast(acc[f][h][3] + b1));
            }
        }
    }
}

// ---------------- stream/event resources (host-side, created once at load) ----------------
namespace {
struct StreamRes {
    cudaStream_t side = nullptr;
    cudaEvent_t ev_fork = nullptr, ev_w = nullptr, ev_e = nullptr;
    StreamRes() {
        cudaStreamCreateWithFlags(&side, cudaStreamNonBlocking);
        cudaEventCreateWithFlags(&ev_fork, cudaEventDisableTiming);
        cudaEventCreateWithFlags(&ev_w, cudaEventDisableTiming);
        cudaEventCreateWithFlags(&ev_e, cudaEventDisableTiming);
    }
};
StreamRes g_sr;
}

// ---------------- launcher: fork prep to side stream, join before k3 / k5 ----------------
extern "C" void kernel_launch(void* const* d_in, const int* in_sizes, int n_in,
                              void* d_out, int out_size) {
    const int*   e1     = (const int*)d_in[0];
    const int*   rel    = (const int*)d_in[1];
    const float* emb    = (const float*)d_in[2];
    const float* conv_w = (const float*)d_in[3];
    const float* conv_b = (const float*)d_in[4];
    const float* g0     = (const float*)d_in[5];
    const float* b0     = (const float*)d_in[6];
    const float* g1     = (const float*)d_in[7];
    const float* b1     = (const float*)d_in[8];
    const float* g2     = (const float*)d_in[9];
    const float* b2     = (const float*)d_in[10];
    const float* fc_w   = (const float*)d_in[11];
    // d_in[12] = fc_b: cancels exactly under training-mode bn2
    const float* bias_e = (const float*)d_in[13];
    float* out = (float*)d_out;

    cudaFuncSetAttribute(k3_mma, cudaFuncAttributeMaxDynamicSharedMemorySize, F_SMEM);
    cudaFuncSetAttribute(k5_mma, cudaFuncAttributeMaxDynamicSharedMemorySize, K5_SMEM);

    // fork side stream off the main (launch) stream
    cudaEventRecord(g_sr.ev_fork, 0);
    cudaStreamWaitEvent(g_sr.side, g_sr.ev_fork, 0);
    k_prep_w<<<PREPW_GRID, 256, 0, g_sr.side>>>(fc_w);
    cudaEventRecord(g_sr.ev_w, g_sr.side);
    k_prep_e<<<PREPE_GRID, 256, 0, g_sr.side>>>(emb);
    cudaEventRecord(g_sr.ev_e, g_sr.side);

    // main chain
    k1_bn0<<<16, 512>>>(e1, emb);
    k2_conv<<<B, 256>>>(e1, rel, emb, conv_w, conv_b, g0, b0);
    cudaStreamWaitEvent(0, g_sr.ev_w, 0);            // k3 needs d_wcat + d_h zero
    k3_mma<<<dim3(2, 8, 72), 256, F_SMEM>>>(g1, b1);
    k4_bn2<<<EDIM, 256>>>(g2, b2);
    cudaStreamWaitEvent(0, g_sr.ev_e, 0);            // k5 needs d_ecat
    k5_mma<<<dim3(8, N_GRID), 256, K5_SMEM>>>(bias_e, out);
}